// round 1
// baseline (speedup 1.0000x reference)
#include <cuda_runtime.h>
#include <math.h>

#define NV   65536
#define CC   64
#define HH   4
#define DD   16
#define KV   125
#define PP   1048576

// Scratch (device globals: allocation-free per harness rules)
__device__ float g_nq[NV * CC];
__device__ float g_nk[NV * CC];
__device__ float g_v [NV * CC];
__device__ float g_acc[NV * CC];
__device__ float g_npos[KV * CC];

// ---------------------------------------------------------------------------
// Kernel 1: fused QKV GEMM + per-head L2 normalization of q,k
// block = 256 threads = (64 cols) x (4 y), each thread computes 4 rows
// => 16 rows per block, grid = 4096
// dynamic smem: Wq,Wk,Wv (3*4096 floats) + X tile (16*64 floats) = 53248 B
// ---------------------------------------------------------------------------
__global__ void __launch_bounds__(256) qkv_kernel(
    const float* __restrict__ x,
    const float* __restrict__ Wq, const float* __restrict__ bq,
    const float* __restrict__ Wk, const float* __restrict__ bk,
    const float* __restrict__ Wv, const float* __restrict__ bv)
{
    extern __shared__ float sm[];
    float* sWq = sm;
    float* sWk = sm + 4096;
    float* sWv = sm + 8192;
    float* sX  = sm + 12288;   // [16][64]

    const int tid = threadIdx.x;
    for (int i = tid; i < 4096; i += 256) {
        sWq[i] = Wq[i];
        sWk[i] = Wk[i];
        sWv[i] = Wv[i];
    }
    const int rowBase = blockIdx.x * 16;
    {
        const float4* xg = (const float4*)(x + (size_t)rowBase * CC);
        float4* sx4 = (float4*)sX;
        for (int i = tid; i < 16 * 16; i += 256) sx4[i] = xg[i];
    }
    __syncthreads();

    const int col = tid & 63;
    const int ry  = tid >> 6;   // 0..3

    float aq[4], ak[4], av[4];
    const float b0 = bq[col], b1 = bk[col], b2 = bv[col];
#pragma unroll
    for (int r = 0; r < 4; r++) { aq[r] = b0; ak[r] = b1; av[r] = b2; }

#pragma unroll 8
    for (int i = 0; i < 64; i++) {
        const float wq = sWq[i * 64 + col];
        const float wk = sWk[i * 64 + col];
        const float wv = sWv[i * 64 + col];
#pragma unroll
        for (int r = 0; r < 4; r++) {
            const float xv = sX[(ry * 4 + r) * 64 + i];
            aq[r] = fmaf(xv, wq, aq[r]);
            ak[r] = fmaf(xv, wk, ak[r]);
            av[r] = fmaf(xv, wv, av[r]);
        }
    }

    // per-head (16-lane) L2 norm for q and k; head groups align with lanes
#pragma unroll
    for (int r = 0; r < 4; r++) {
        const int row = rowBase + ry * 4 + r;

        float sq = aq[r] * aq[r];
        sq += __shfl_xor_sync(0xffffffffu, sq, 1, 16);
        sq += __shfl_xor_sync(0xffffffffu, sq, 2, 16);
        sq += __shfl_xor_sync(0xffffffffu, sq, 4, 16);
        sq += __shfl_xor_sync(0xffffffffu, sq, 8, 16);
        const float invq = 1.0f / fmaxf(sqrtf(sq), 1e-12f);

        float sk = ak[r] * ak[r];
        sk += __shfl_xor_sync(0xffffffffu, sk, 1, 16);
        sk += __shfl_xor_sync(0xffffffffu, sk, 2, 16);
        sk += __shfl_xor_sync(0xffffffffu, sk, 4, 16);
        sk += __shfl_xor_sync(0xffffffffu, sk, 8, 16);
        const float invk = 1.0f / fmaxf(sqrtf(sk), 1e-12f);

        g_nq[(size_t)row * 64 + col] = aq[r] * invq;
        g_nk[(size_t)row * 64 + col] = ak[r] * invk;
        g_v [(size_t)row * 64 + col] = av[r];
    }
}

// ---------------------------------------------------------------------------
// Kernel 2: L2-normalize pos_enc [125][4][16] -> g_npos
// ---------------------------------------------------------------------------
__global__ void pos_kernel(const float* __restrict__ pe)
{
    const int t = blockIdx.x * blockDim.x + threadIdx.x;
    if (t >= KV * HH) return;
    const float* src = pe + (size_t)t * DD;
    float v[DD];
    float s = 0.f;
#pragma unroll
    for (int j = 0; j < DD; j++) { v[j] = src[j]; s += v[j] * v[j]; }
    const float inv = 1.0f / fmaxf(sqrtf(s), 1e-12f);
#pragma unroll
    for (int j = 0; j < DD; j++) g_npos[(size_t)t * DD + j] = v[j] * inv;
}

// ---------------------------------------------------------------------------
// Kernel 3: per-pair attention + scatter-add into g_acc
// one thread per (pair, head): P*H = 4M threads
// ---------------------------------------------------------------------------
__device__ __forceinline__ void red_add_v4(float* addr, float a, float b, float c, float d)
{
    asm volatile("red.global.add.v4.f32 [%0], {%1, %2, %3, %4};"
                 :: "l"(addr), "f"(a), "f"(b), "f"(c), "f"(d)
                 : "memory");
}

__global__ void __launch_bounds__(256) pair_kernel(const int* __restrict__ kq)
{
    const int t = blockIdx.x * 256 + threadIdx.x;
    const int p = t >> 2;
    const int h = t & 3;

    const int a    = __ldg(kq + p);
    const int outi = __ldg(kq + PP + p);
    const int ini  = a / KV;
    const int kidx = a - ini * KV;

    const float4* q4  = (const float4*)(g_nq   + (size_t)outi * CC + h * DD);
    const float4* k4  = (const float4*)(g_nk   + (size_t)ini  * CC + h * DD);
    const float4* pe4 = (const float4*)(g_npos + (size_t)kidx * CC + h * DD);

    float attn = 0.f;
#pragma unroll
    for (int j = 0; j < 4; j++) {
        const float4 q = q4[j];
        const float4 k = k4[j];
        const float4 e = pe4[j];
        attn += q.x * (k.x + e.x) + q.y * (k.y + e.y)
              + q.z * (k.z + e.z) + q.w * (k.w + e.w);
    }

    const float4* v4 = (const float4*)(g_v + (size_t)ini * CC + h * DD);
    float* acc = g_acc + (size_t)outi * CC + h * DD;
#pragma unroll
    for (int j = 0; j < 4; j++) {
        const float4 v = v4[j];
        red_add_v4(acc + j * 4, attn * v.x, attn * v.y, attn * v.z, attn * v.w);
    }
}

// ---------------------------------------------------------------------------
// Kernel 4: out = g_acc @ Wo + bo + x  -> d_out
// same structure as qkv_kernel, single weight matrix (static smem 20 KB)
// ---------------------------------------------------------------------------
__global__ void __launch_bounds__(256) out_kernel(
    const float* __restrict__ Wo, const float* __restrict__ bo,
    const float* __restrict__ x, float* __restrict__ out)
{
    __shared__ float sW[4096];
    __shared__ float sA[16 * 64];

    const int tid = threadIdx.x;
    for (int i = tid; i < 4096; i += 256) sW[i] = Wo[i];
    const int rowBase = blockIdx.x * 16;
    {
        const float4* ag = (const float4*)(g_acc + (size_t)rowBase * CC);
        float4* sa4 = (float4*)sA;
        for (int i = tid; i < 16 * 16; i += 256) sa4[i] = ag[i];
    }
    __syncthreads();

    const int col = tid & 63;
    const int ry  = tid >> 6;

    float o[4];
    const float bb = bo[col];
#pragma unroll
    for (int r = 0; r < 4; r++) o[r] = bb;

#pragma unroll 8
    for (int i = 0; i < 64; i++) {
        const float w = sW[i * 64 + col];
#pragma unroll
        for (int r = 0; r < 4; r++) {
            o[r] = fmaf(sA[(ry * 4 + r) * 64 + i], w, o[r]);
        }
    }

#pragma unroll
    for (int r = 0; r < 4; r++) {
        const size_t idx = (size_t)(rowBase + ry * 4 + r) * CC + col;
        out[idx] = o[r] + x[idx];
    }
}

// ---------------------------------------------------------------------------
extern "C" void kernel_launch(void* const* d_in, const int* in_sizes, int n_in,
                              void* d_out, int out_size)
{
    const float* x  = (const float*)d_in[0];
    const float* Wq = (const float*)d_in[1];
    const float* bq = (const float*)d_in[2];
    const float* Wk = (const float*)d_in[3];
    const float* bk = (const float*)d_in[4];
    const float* Wv = (const float*)d_in[5];
    const float* bv = (const float*)d_in[6];
    const float* Wo = (const float*)d_in[7];
    const float* bo = (const float*)d_in[8];
    const float* pe = (const float*)d_in[9];
    const int*   kq = (const int*)d_in[10];
    float* out = (float*)d_out;

    // zero the scatter accumulator
    void* accPtr = nullptr;
    cudaGetSymbolAddress(&accPtr, g_acc);
    cudaMemsetAsync(accPtr, 0, (size_t)NV * CC * sizeof(float));

    // opt-in to 52 KB dynamic smem for the QKV kernel (no-op after first call)
    const int smemBytes = (3 * 4096 + 16 * 64) * (int)sizeof(float); // 53248
    cudaFuncSetAttribute(qkv_kernel, cudaFuncAttributeMaxDynamicSharedMemorySize, smemBytes);

    qkv_kernel<<<NV / 16, 256, smemBytes>>>(x, Wq, bq, Wk, bk, Wv, bv);
    pos_kernel<<<(KV * HH + 255) / 256, 256>>>(pe);
    pair_kernel<<<(PP * HH) / 256, 256>>>(kq);
    out_kernel<<<NV / 16, 256>>>(Wo, bo, x, out);
}

// round 2
// speedup vs baseline: 1.1279x; 1.1279x over previous
#include <cuda_runtime.h>
#include <math.h>

#define NV   65536
#define CC   64
#define HH   4
#define DD   16
#define KV   125
#define PP   1048576

// Scratch (device globals: allocation-free per harness rules)
__device__ float g_nq[NV * CC];
__device__ float g_nk[NV * CC];
__device__ float g_v [NV * CC];
__device__ float g_acc[NV * CC];
__device__ float g_npos[KV * CC];

// ---- packed fp32x2 helpers (Blackwell FFMA2) --------------------------------
__device__ __forceinline__ unsigned long long ffma2(unsigned long long a,
                                                    unsigned long long b,
                                                    unsigned long long c)
{
    unsigned long long d;
    asm("fma.rn.f32x2 %0, %1, %2, %3;" : "=l"(d) : "l"(a), "l"(b), "l"(c));
    return d;
}
__device__ __forceinline__ unsigned long long pack2(float x, float y)
{
    unsigned long long d;
    asm("mov.b64 %0, {%1, %2};" : "=l"(d) : "f"(x), "f"(y));
    return d;
}
__device__ __forceinline__ void unpack2(unsigned long long v, float& x, float& y)
{
    asm("mov.b64 {%0, %1}, %2;" : "=f"(x), "=f"(y) : "l"(v));
}

#define XSTRIDE 68   // padded row stride (floats) of transposed x tile; 16B-aligned

// ---------------------------------------------------------------------------
// Kernel 1: fused QKV GEMM + per-head L2 norm.  64 rows/block, 4x4 reg tiles,
// FFMA2 packed math. Also zeroes its 64 rows of g_acc (replaces memset).
// dyn smem: Wq/Wk/Wv (3*4096) + sXT (64*68) floats = 66560 B
// ---------------------------------------------------------------------------
__global__ void __launch_bounds__(256) qkv_kernel(
    const float* __restrict__ x,
    const float* __restrict__ Wq, const float* __restrict__ bq,
    const float* __restrict__ Wk, const float* __restrict__ bk,
    const float* __restrict__ Wv, const float* __restrict__ bv)
{
    extern __shared__ float sm[];
    float* sWq = sm;
    float* sWk = sm + 4096;
    float* sWv = sm + 8192;
    float* sXT = sm + 12288;            // [64 k][68 pad] transposed x tile

    const int tid = threadIdx.x;
    const int rowBase = blockIdx.x * 64;

    for (int i = tid; i < 4096; i += 256) {
        sWq[i] = Wq[i];
        sWk[i] = Wk[i];
        sWv[i] = Wv[i];
    }
    // load + transpose x tile; also zero our slice of g_acc
    {
        const float4* xg = (const float4*)(x + (size_t)rowBase * CC);
        float4* acc4 = (float4*)(g_acc + (size_t)rowBase * CC);
        const float4 z = make_float4(0.f, 0.f, 0.f, 0.f);
#pragma unroll
        for (int k = 0; k < 4; k++) {
            const int idx = k * 256 + tid;        // 0..1023 float4s
            const int row = idx >> 4;
            const int c4  = (idx & 15) * 4;
            const float4 xv = xg[idx];
            sXT[(c4 + 0) * XSTRIDE + row] = xv.x;
            sXT[(c4 + 1) * XSTRIDE + row] = xv.y;
            sXT[(c4 + 2) * XSTRIDE + row] = xv.z;
            sXT[(c4 + 3) * XSTRIDE + row] = xv.w;
            acc4[idx] = z;
        }
    }
    __syncthreads();

    const int tc = tid & 15;
    const int tr = tid >> 4;
    const int col4 = tc * 4;
    const int r0   = tr * 4;

    unsigned long long q01[4], q23[4], k01[4], k23[4], v01[4], v23[4];
    {
        const float4 b4q = *(const float4*)&bq[col4];
        const float4 b4k = *(const float4*)&bk[col4];
        const float4 b4v = *(const float4*)&bv[col4];
        const unsigned long long iq01 = pack2(b4q.x, b4q.y), iq23 = pack2(b4q.z, b4q.w);
        const unsigned long long ik01 = pack2(b4k.x, b4k.y), ik23 = pack2(b4k.z, b4k.w);
        const unsigned long long iv01 = pack2(b4v.x, b4v.y), iv23 = pack2(b4v.z, b4v.w);
#pragma unroll
        for (int r = 0; r < 4; r++) {
            q01[r] = iq01; q23[r] = iq23;
            k01[r] = ik01; k23[r] = ik23;
            v01[r] = iv01; v23[r] = iv23;
        }
    }

#pragma unroll 8
    for (int i = 0; i < 64; i++) {
        const float4 x4 = *(const float4*)&sXT[i * XSTRIDE + r0];
        unsigned long long xx[4];
        xx[0] = pack2(x4.x, x4.x);
        xx[1] = pack2(x4.y, x4.y);
        xx[2] = pack2(x4.z, x4.z);
        xx[3] = pack2(x4.w, x4.w);
        const unsigned long long* wq = (const unsigned long long*)&sWq[i * 64 + col4];
        const unsigned long long* wk = (const unsigned long long*)&sWk[i * 64 + col4];
        const unsigned long long* wv = (const unsigned long long*)&sWv[i * 64 + col4];
        const unsigned long long wq0 = wq[0], wq1 = wq[1];
        const unsigned long long wk0 = wk[0], wk1 = wk[1];
        const unsigned long long wv0 = wv[0], wv1 = wv[1];
#pragma unroll
        for (int r = 0; r < 4; r++) {
            q01[r] = ffma2(xx[r], wq0, q01[r]);
            q23[r] = ffma2(xx[r], wq1, q23[r]);
            k01[r] = ffma2(xx[r], wk0, k01[r]);
            k23[r] = ffma2(xx[r], wk1, k23[r]);
            v01[r] = ffma2(xx[r], wv0, v01[r]);
            v23[r] = ffma2(xx[r], wv1, v23[r]);
        }
    }

    // per-head L2 norm: head = col4/16; a head's 16 cols live on 4 adjacent
    // lanes (tc = 4h..4h+3), same tr -> 4-wide shfl reduction per row.
#pragma unroll
    for (int r = 0; r < 4; r++) {
        const int row = rowBase + r0 + r;
        float q0, q1, q2, q3, k0, k1, k2, k3, v0, v1, v2, v3;
        unpack2(q01[r], q0, q1); unpack2(q23[r], q2, q3);
        unpack2(k01[r], k0, k1); unpack2(k23[r], k2, k3);
        unpack2(v01[r], v0, v1); unpack2(v23[r], v2, v3);

        float sq = q0*q0 + q1*q1 + q2*q2 + q3*q3;
        sq += __shfl_xor_sync(0xffffffffu, sq, 1, 4);
        sq += __shfl_xor_sync(0xffffffffu, sq, 2, 4);
        const float invq = 1.0f / fmaxf(sqrtf(sq), 1e-12f);

        float sk = k0*k0 + k1*k1 + k2*k2 + k3*k3;
        sk += __shfl_xor_sync(0xffffffffu, sk, 1, 4);
        sk += __shfl_xor_sync(0xffffffffu, sk, 2, 4);
        const float invk = 1.0f / fmaxf(sqrtf(sk), 1e-12f);

        *(float4*)&g_nq[(size_t)row * CC + col4] = make_float4(q0*invq, q1*invq, q2*invq, q3*invq);
        *(float4*)&g_nk[(size_t)row * CC + col4] = make_float4(k0*invk, k1*invk, k2*invk, k3*invk);
        *(float4*)&g_v [(size_t)row * CC + col4] = make_float4(v0, v1, v2, v3);
    }
}

// ---------------------------------------------------------------------------
// Kernel 2: L2-normalize pos_enc [125][4][16] -> g_npos
// ---------------------------------------------------------------------------
__global__ void pos_kernel(const float* __restrict__ pe)
{
    const int t = blockIdx.x * blockDim.x + threadIdx.x;
    if (t >= KV * HH) return;
    const float* src = pe + (size_t)t * DD;
    float v[DD];
    float s = 0.f;
#pragma unroll
    for (int j = 0; j < DD; j++) { v[j] = src[j]; s += v[j] * v[j]; }
    const float inv = 1.0f / fmaxf(sqrtf(s), 1e-12f);
#pragma unroll
    for (int j = 0; j < DD; j++) g_npos[(size_t)t * DD + j] = v[j] * inv;
}

// ---------------------------------------------------------------------------
// Kernel 3: per-pair attention + scatter-add into g_acc
// one thread per (pair, head): P*H = 4M threads; heads of a pair share a warp
// so all row loads coalesce to full 256B rows.
// ---------------------------------------------------------------------------
__device__ __forceinline__ void red_add_v4(float* addr, float a, float b, float c, float d)
{
    asm volatile("red.global.add.v4.f32 [%0], {%1, %2, %3, %4};"
                 :: "l"(addr), "f"(a), "f"(b), "f"(c), "f"(d)
                 : "memory");
}

__global__ void __launch_bounds__(256) pair_kernel(const int* __restrict__ kq)
{
    const int t = blockIdx.x * 256 + threadIdx.x;
    const int p = t >> 2;
    const int h = t & 3;

    const int a    = __ldg(kq + p);
    const int outi = __ldg(kq + PP + p);
    const int ini  = a / KV;
    const int kidx = a - ini * KV;

    const float4* q4  = (const float4*)(g_nq   + (size_t)outi * CC + h * DD);
    const float4* k4  = (const float4*)(g_nk   + (size_t)ini  * CC + h * DD);
    const float4* pe4 = (const float4*)(g_npos + (size_t)kidx * CC + h * DD);

    float attn = 0.f;
#pragma unroll
    for (int j = 0; j < 4; j++) {
        const float4 q = q4[j];
        const float4 k = k4[j];
        const float4 e = pe4[j];
        attn += q.x * (k.x + e.x) + q.y * (k.y + e.y)
              + q.z * (k.z + e.z) + q.w * (k.w + e.w);
    }

    const float4* v4 = (const float4*)(g_v + (size_t)ini * CC + h * DD);
    float* acc = g_acc + (size_t)outi * CC + h * DD;
#pragma unroll
    for (int j = 0; j < 4; j++) {
        const float4 v = v4[j];
        red_add_v4(acc + j * 4, attn * v.x, attn * v.y, attn * v.z, attn * v.w);
    }
}

// ---------------------------------------------------------------------------
// Kernel 4: out = g_acc @ Wo + bo + x  -> d_out.  Same 4x4/FFMA2 structure.
// ---------------------------------------------------------------------------
__global__ void __launch_bounds__(256) out_kernel(
    const float* __restrict__ Wo, const float* __restrict__ bo,
    const float* __restrict__ x, float* __restrict__ out)
{
    __shared__ float sW[4096];
    __shared__ float sXT[64 * XSTRIDE];

    const int tid = threadIdx.x;
    const int rowBase = blockIdx.x * 64;

    for (int i = tid; i < 4096; i += 256) sW[i] = Wo[i];
    {
        const float4* ag = (const float4*)(g_acc + (size_t)rowBase * CC);
#pragma unroll
        for (int k = 0; k < 4; k++) {
            const int idx = k * 256 + tid;
            const int row = idx >> 4;
            const int c4  = (idx & 15) * 4;
            const float4 av = ag[idx];
            sXT[(c4 + 0) * XSTRIDE + row] = av.x;
            sXT[(c4 + 1) * XSTRIDE + row] = av.y;
            sXT[(c4 + 2) * XSTRIDE + row] = av.z;
            sXT[(c4 + 3) * XSTRIDE + row] = av.w;
        }
    }
    __syncthreads();

    const int tc = tid & 15;
    const int tr = tid >> 4;
    const int col4 = tc * 4;
    const int r0   = tr * 4;

    unsigned long long o01[4], o23[4];
    {
        const float4 b4 = *(const float4*)&bo[col4];
        const unsigned long long i01 = pack2(b4.x, b4.y), i23 = pack2(b4.z, b4.w);
#pragma unroll
        for (int r = 0; r < 4; r++) { o01[r] = i01; o23[r] = i23; }
    }

#pragma unroll 8
    for (int i = 0; i < 64; i++) {
        const float4 x4 = *(const float4*)&sXT[i * XSTRIDE + r0];
        unsigned long long xx[4];
        xx[0] = pack2(x4.x, x4.x);
        xx[1] = pack2(x4.y, x4.y);
        xx[2] = pack2(x4.z, x4.z);
        xx[3] = pack2(x4.w, x4.w);
        const unsigned long long* w = (const unsigned long long*)&sW[i * 64 + col4];
        const unsigned long long w0 = w[0], w1 = w[1];
#pragma unroll
        for (int r = 0; r < 4; r++) {
            o01[r] = ffma2(xx[r], w0, o01[r]);
            o23[r] = ffma2(xx[r], w1, o23[r]);
        }
    }

#pragma unroll
    for (int r = 0; r < 4; r++) {
        const size_t base = (size_t)(rowBase + r0 + r) * CC + col4;
        float o0, o1, o2, o3;
        unpack2(o01[r], o0, o1);
        unpack2(o23[r], o2, o3);
        const float4 xr = *(const float4*)&x[base];
        *(float4*)&out[base] = make_float4(o0 + xr.x, o1 + xr.y, o2 + xr.z, o3 + xr.w);
    }
}

// ---------------------------------------------------------------------------
extern "C" void kernel_launch(void* const* d_in, const int* in_sizes, int n_in,
                              void* d_out, int out_size)
{
    const float* x  = (const float*)d_in[0];
    const float* Wq = (const float*)d_in[1];
    const float* bq = (const float*)d_in[2];
    const float* Wk = (const float*)d_in[3];
    const float* bk = (const float*)d_in[4];
    const float* Wv = (const float*)d_in[5];
    const float* bv = (const float*)d_in[6];
    const float* Wo = (const float*)d_in[7];
    const float* bo = (const float*)d_in[8];
    const float* pe = (const float*)d_in[9];
    const int*   kq = (const int*)d_in[10];
    float* out = (float*)d_out;

    const int smemBytes = (3 * 4096 + 64 * XSTRIDE) * (int)sizeof(float); // 66560
    cudaFuncSetAttribute(qkv_kernel, cudaFuncAttributeMaxDynamicSharedMemorySize, smemBytes);

    qkv_kernel<<<NV / 64, 256, smemBytes>>>(x, Wq, bq, Wk, bk, Wv, bv);
    pos_kernel<<<(KV * HH + 255) / 256, 256>>>(pe);
    pair_kernel<<<(PP * HH) / 256, 256>>>(kq);
    out_kernel<<<NV / 64, 256>>>(Wo, bo, x, out);
}